// round 2
// baseline (speedup 1.0000x reference)
#include <cuda_runtime.h>

#define BB 32
#define CC 64
#define HH 64
#define WW 64
#define EE 8
#define HWC (HH*WW)

// Scratch (device globals: no allocation allowed)
__device__ float g_S[BB * 9 * CC];   // box sums, layout [(b*9+k)*C + c], k = di*3+dj
__device__ float g_val[BB];
__device__ int   g_idx[BB];

// Packed fp32x2 helpers (sm_103a dual-rate fp32 pipe, PTX-only)
#define FMA2(d, a, b, c) \
    asm("fma.rn.f32x2 %0, %1, %2, %3;" : "=l"(d) : "l"(a), "l"(b), "l"(c))
#define MUL2(d, a, b) \
    asm("mul.rn.f32x2 %0, %1, %2;" : "=l"(d) : "l"(a), "l"(b))
#define PACK2(d, f) \
    asm("mov.b64 %0, {%1, %1};" : "=l"(d) : "f"(f))

// ---------------------------------------------------------------------------
// Kernel 1: box sums. 512 blocks x 256 threads; each block handles 4 images
// (bc = blockIdx.x*4 + tid>>6); each thread reads one full 64-float row
// (16 independent float4 loads, MLP=16). Warp-shuffle reduction.
// ---------------------------------------------------------------------------
__global__ __launch_bounds__(256) void region_sums_kernel(const float* __restrict__ x) {
    int tid = threadIdx.x;
    int img = tid >> 6;               // 0..3 local image
    int r   = tid & 63;               // row
    int bc  = blockIdx.x * 4 + img;

    const float4* p = (const float4*)(x + (size_t)bc * HWC + r * WW);
    float4 v[16];
    #pragma unroll
    for (int i = 0; i < 16; i++) v[i] = p[i];

    float rs = 0.f;
    #pragma unroll
    for (int i = 0; i < 16; i++) rs += (v[i].x + v[i].y) + (v[i].z + v[i].w);

    float eL0 = v[0].x,  eL1 = v[0].y;    // x[r][0], x[r][1]
    float eR0 = v[15].z, eR1 = v[15].w;   // x[r][62], x[r][63]

    float cv0 = rs - eR0 - eR1;   // cols 0..61
    float cv1 = rs - eL0 - eR1;   // cols 1..62
    float cv2 = rs - eL0 - eL1;   // cols 2..63

    __shared__ float sCv[4][3][64];
    __shared__ float part[8][3];
    sCv[img][0][r] = cv0;
    sCv[img][1][r] = cv1;
    sCv[img][2][r] = cv2;

    float t0 = cv0, t1 = cv1, t2 = cv2;
    #pragma unroll
    for (int o = 16; o; o >>= 1) {
        t0 += __shfl_down_sync(0xffffffffu, t0, o);
        t1 += __shfl_down_sync(0xffffffffu, t1, o);
        t2 += __shfl_down_sync(0xffffffffu, t2, o);
    }
    int warp = tid >> 5;
    if ((tid & 31) == 0) { part[warp][0] = t0; part[warp][1] = t1; part[warp][2] = t2; }
    __syncthreads();

    if (r < 3) {
        int dj = r;
        float T = part[2*img][dj] + part[2*img+1][dj];
        int b = bc >> 6, c = bc & 63;
        float c62 = sCv[img][dj][62], c63 = sCv[img][dj][63];
        float c0  = sCv[img][dj][0],  c1  = sCv[img][dj][1];
        g_S[(b*9 + 0*3 + dj)*CC + c] = T - c62 - c63;  // rows 0..61
        g_S[(b*9 + 1*3 + dj)*CC + c] = T - c0  - c63;  // rows 1..62
        g_S[(b*9 + 2*3 + dj)*CC + c] = T - c0  - c1;   // rows 2..63
    }
}

// ---------------------------------------------------------------------------
// Kernel 2: gating dot products, softmax, top-1, expert_weights output.
// One block per b, 256 threads (warp e handles expert e).
// ---------------------------------------------------------------------------
__global__ __launch_bounds__(256) void gate_kernel(const float* __restrict__ gate_w,
                                                   const float* __restrict__ gate_b,
                                                   float* __restrict__ ew_out,
                                                   int write_ew) {
    int b = blockIdx.x;
    int tid = threadIdx.x;
    __shared__ float Ssh[9 * 64];          // [k*64 + c]
    __shared__ float gat[8];

    for (int i = tid; i < 576; i += 256) Ssh[i] = g_S[b*576 + i];
    __syncthreads();

    int warp = tid >> 5, lane = tid & 31;  // warp = expert index
    float acc = 0.f;
    for (int idx = lane; idx < 576; idx += 32) {
        int c = idx / 9;
        int k = idx - c * 9;
        acc += gate_w[warp * 576 + idx] * Ssh[k * 64 + c];
    }
    #pragma unroll
    for (int o = 16; o; o >>= 1) acc += __shfl_down_sync(0xffffffffu, acc, o);
    if (lane == 0) gat[warp] = acc + gate_b[warp] * 3844.0f;  // 62*62 positions
    __syncthreads();

    if (tid == 0) {
        float m = gat[0]; int mi = 0;
        #pragma unroll
        for (int e = 1; e < 8; e++) { if (gat[e] > m) { m = gat[e]; mi = e; } }
        float s = 0.f;
        #pragma unroll
        for (int e = 0; e < 8; e++) s += expf(gat[e] - m);
        g_val[b] = 1.0f / s;
        g_idx[b] = mi;
    }
    __syncthreads();
    if (write_ew && tid < 8) {
        ew_out[b * 8 + tid] = (tid == g_idx[b]) ? g_val[b] : 0.0f;
    }
}

// ---------------------------------------------------------------------------
// Kernel 3: out[b] = val[b] * W[idx[b]] @ x[b]  via packed f32x2 FMA.
// GEMM: M=64 (f), N=4096 (hw), K=64 (c). Block: 64f x 128hw, full K.
// Thread (tf,th): 4f x 8hw = 16 f32x2 accumulators (pairs along hw).
// ---------------------------------------------------------------------------
__global__ __launch_bounds__(256) void moe_gemm_kernel(const float* __restrict__ x,
                                                       const float* __restrict__ expert_w,
                                                       float* __restrict__ out) {
    __shared__ __align__(16) float Ws[64 * 64];    // [c*64 + (f ^ (c&31))]
    __shared__ __align__(16) float Xs[64 * 128];   // [c*128 + j]

    int b   = blockIdx.y;
    int hw0 = blockIdx.x * 128;
    int e   = g_idx[b];
    float val = g_val[b];

    const float* Wsrc = expert_w + (size_t)e * 64 * 64;   // [f][c]
    const float* Xsrc = x + (size_t)b * CC * HWC + hw0;
    int tid = threadIdx.x;

    // Load W transposed with per-element swizzle (coalesced gmem, conflict-free STS)
    #pragma unroll
    for (int i = tid; i < 4096; i += 256) {
        int f = i >> 6, c = i & 63;
        Ws[c * 64 + (f ^ (c & 31))] = Wsrc[i];
    }
    // Load X tile: 64 rows x 128 floats
    {
        int lane = tid & 31;
        int crow = tid >> 5;   // 0..7
        #pragma unroll
        for (int pass = 0; pass < 8; pass++) {
            int c = pass * 8 + crow;
            float4 v = *(const float4*)(Xsrc + (size_t)c * HWC + lane * 4);
            *(float4*)(Xs + c * 128 + lane * 4) = v;
        }
    }
    __syncthreads();

    int tf = tid >> 4;       // 0..15
    int th = tid & 15;       // 0..15
    int f0 = tf * 4;
    int j0 = th * 8;

    unsigned long long acc[4][4];   // [f][hw-pair]
    #pragma unroll
    for (int i = 0; i < 4; i++)
        #pragma unroll
        for (int j = 0; j < 4; j++) acc[i][j] = 0ull;

    #pragma unroll 8
    for (int c = 0; c < 64; c++) {
        int sw = c & 31;
        const float* wrow = Ws + c * 64;
        float w0 = wrow[(f0 + 0) ^ sw];
        float w1 = wrow[(f0 + 1) ^ sw];
        float w2 = wrow[(f0 + 2) ^ sw];
        float w3 = wrow[(f0 + 3) ^ sw];
        unsigned long long wp0, wp1, wp2, wp3;
        PACK2(wp0, w0); PACK2(wp1, w1); PACK2(wp2, w2); PACK2(wp3, w3);

        ulonglong2 xa = *(const ulonglong2*)(Xs + c * 128 + j0);      // (x0,x1),(x2,x3)
        ulonglong2 xb = *(const ulonglong2*)(Xs + c * 128 + j0 + 4);  // (x4,x5),(x6,x7)

        FMA2(acc[0][0], wp0, xa.x, acc[0][0]);
        FMA2(acc[0][1], wp0, xa.y, acc[0][1]);
        FMA2(acc[0][2], wp0, xb.x, acc[0][2]);
        FMA2(acc[0][3], wp0, xb.y, acc[0][3]);
        FMA2(acc[1][0], wp1, xa.x, acc[1][0]);
        FMA2(acc[1][1], wp1, xa.y, acc[1][1]);
        FMA2(acc[1][2], wp1, xb.x, acc[1][2]);
        FMA2(acc[1][3], wp1, xb.y, acc[1][3]);
        FMA2(acc[2][0], wp2, xa.x, acc[2][0]);
        FMA2(acc[2][1], wp2, xa.y, acc[2][1]);
        FMA2(acc[2][2], wp2, xb.x, acc[2][2]);
        FMA2(acc[2][3], wp2, xb.y, acc[2][3]);
        FMA2(acc[3][0], wp3, xa.x, acc[3][0]);
        FMA2(acc[3][1], wp3, xa.y, acc[3][1]);
        FMA2(acc[3][2], wp3, xb.x, acc[3][2]);
        FMA2(acc[3][3], wp3, xb.y, acc[3][3]);
    }

    unsigned long long vp;
    PACK2(vp, val);
    float* outp = out + (size_t)b * CC * HWC + hw0;
    #pragma unroll
    for (int ff = 0; ff < 4; ff++) {
        unsigned long long r0, r1, r2, r3;
        MUL2(r0, acc[ff][0], vp);
        MUL2(r1, acc[ff][1], vp);
        MUL2(r2, acc[ff][2], vp);
        MUL2(r3, acc[ff][3], vp);
        ulonglong2 s0; s0.x = r0; s0.y = r1;
        ulonglong2 s1; s1.x = r2; s1.y = r3;
        *(ulonglong2*)(outp + (size_t)(f0 + ff) * HWC + j0)     = s0;
        *(ulonglong2*)(outp + (size_t)(f0 + ff) * HWC + j0 + 4) = s1;
    }
}

// ---------------------------------------------------------------------------
extern "C" void kernel_launch(void* const* d_in, const int* in_sizes, int n_in,
                              void* d_out, int out_size) {
    const float* x = nullptr, *gate_w = nullptr, *gate_b = nullptr, *expert_w = nullptr;
    for (int i = 0; i < n_in; i++) {
        switch (in_sizes[i]) {
            case BB*CC*HH*WW: x        = (const float*)d_in[i]; break;  // 524288
            case EE*CC*3*3:   gate_w   = (const float*)d_in[i]; break;  // 4608
            case EE:          gate_b   = (const float*)d_in[i]; break;  // 8
            case EE*CC*CC:    expert_w = (const float*)d_in[i]; break;  // 32768
            default: break;
        }
    }
    float* out = (float*)d_out;
    const int main_elems = BB * CC * HH * WW;
    int write_ew = (out_size >= main_elems + BB * EE) ? 1 : 0;

    region_sums_kernel<<<(BB * CC) / 4, 256>>>(x);
    gate_kernel<<<BB, 256>>>(gate_w, gate_b, out + main_elems, write_ew);
    moe_gemm_kernel<<<dim3(HWC / 128, BB), 256>>>(x, expert_w, out);
}

// round 4
// speedup vs baseline: 1.7543x; 1.7543x over previous
#include <cuda_runtime.h>
#include <cuda_bf16.h>
#include <cstdint>

#define BB 32
#define CC 64
#define HH 64
#define WW 64
#define EE 8
#define HWC (HH*WW)

// Scratch (device globals: no allocation allowed)
__device__ float g_S[BB * 9 * CC];   // box sums, layout [(b*9+k)*C + c], k = di*3+dj
__device__ float g_val[BB];
__device__ int   g_idx[BB];

// ===========================================================================
// helpers
// ===========================================================================
__device__ __forceinline__ uint32_t smem_u32(const void* p) {
    uint32_t a;
    asm("{ .reg .u64 t; cvta.to.shared.u64 t, %1; cvt.u32.u64 %0, t; }" : "=r"(a) : "l"(p));
    return a;
}

// pack two floats -> bf16x2 word: low 16 bits = 'even', high = 'odd'
__device__ __forceinline__ uint32_t pack_bf16x2(float even, float odd) {
    uint32_t u;
    asm("cvt.rn.bf16x2.f32 %0, %1, %2;" : "=r"(u) : "f"(odd), "f"(even));
    return u;
}

#define LDMATRIX_X4(R, addr) \
    asm volatile("ldmatrix.sync.aligned.m8n8.x4.shared.b16 {%0,%1,%2,%3}, [%4];" \
        : "=r"((R)[0]), "=r"((R)[1]), "=r"((R)[2]), "=r"((R)[3]) : "r"(addr))

#define LDMATRIX_X2T(R, addr) \
    asm volatile("ldmatrix.sync.aligned.m8n8.x2.trans.shared.b16 {%0,%1}, [%2];" \
        : "=r"((R)[0]), "=r"((R)[1]) : "r"(addr))

#define MMA_BF16(D, A, B0, B1) \
    asm volatile("mma.sync.aligned.m16n8k16.row.col.f32.bf16.bf16.f32 " \
        "{%0,%1,%2,%3}, {%4,%5,%6,%7}, {%8,%9}, {%0,%1,%2,%3};" \
        : "+f"((D)[0]), "+f"((D)[1]), "+f"((D)[2]), "+f"((D)[3]) \
        : "r"((A)[0]), "r"((A)[1]), "r"((A)[2]), "r"((A)[3]), "r"(B0), "r"(B1))

// ===========================================================================
// Kernel 1: box sums. 2048 blocks x 128 threads; thread = half row (8 x float4).
// ===========================================================================
__global__ __launch_bounds__(128) void region_sums_kernel(const float* __restrict__ x) {
    int tid = threadIdx.x;
    int r = tid >> 1, half = tid & 1;
    const float4* p = (const float4*)(x + (size_t)blockIdx.x * HWC + r * WW + half * 32);
    float4 v[8];
    #pragma unroll
    for (int i = 0; i < 8; i++) v[i] = p[i];
    float hs = 0.f;
    #pragma unroll
    for (int i = 0; i < 8; i++) hs += (v[i].x + v[i].y) + (v[i].z + v[i].w);
    float rs = hs + __shfl_xor_sync(0xffffffffu, hs, 1);

    float eA = half ? v[7].z : v[0].x;   // even: x[r][0] ; odd: x[r][62]
    float eB = half ? v[7].w : v[0].y;   // even: x[r][1] ; odd: x[r][63]
    float pA = __shfl_xor_sync(0xffffffffu, eA, 1);
    float pB = __shfl_xor_sync(0xffffffffu, eB, 1);

    __shared__ float sE[3][4];   // [dj][row in {0,1,62,63}]
    __shared__ float sP[4][3];   // warp partials

    float cv0 = 0.f, cv1 = 0.f, cv2 = 0.f;
    if (!half) {
        cv0 = rs - pA - pB;   // cols 0..61
        cv1 = rs - eA - pB;   // cols 1..62
        cv2 = rs - eA - eB;   // cols 2..63
        int ei = (r == 0) ? 0 : (r == 1) ? 1 : (r == 62) ? 2 : (r == 63) ? 3 : -1;
        if (ei >= 0) { sE[0][ei] = cv0; sE[1][ei] = cv1; sE[2][ei] = cv2; }
    }
    #pragma unroll
    for (int o = 16; o; o >>= 1) {
        cv0 += __shfl_xor_sync(0xffffffffu, cv0, o);
        cv1 += __shfl_xor_sync(0xffffffffu, cv1, o);
        cv2 += __shfl_xor_sync(0xffffffffu, cv2, o);
    }
    if ((tid & 31) == 0) { int w = tid >> 5; sP[w][0] = cv0; sP[w][1] = cv1; sP[w][2] = cv2; }
    __syncthreads();

    if (tid < 3) {
        int dj = tid;
        float T = (sP[0][dj] + sP[1][dj]) + (sP[2][dj] + sP[3][dj]);
        int b = blockIdx.x >> 6, c = blockIdx.x & 63;
        g_S[(b*9 + 0 + dj)*CC + c] = T - sE[dj][2] - sE[dj][3];  // rows 0..61
        g_S[(b*9 + 3 + dj)*CC + c] = T - sE[dj][0] - sE[dj][3];  // rows 1..62
        g_S[(b*9 + 6 + dj)*CC + c] = T - sE[dj][0] - sE[dj][1];  // rows 2..63
    }
}

// ===========================================================================
// Kernel 2: gating dot products, softmax, top-1, expert_weights output.
// ===========================================================================
__global__ __launch_bounds__(256) void gate_kernel(const float* __restrict__ gate_w,
                                                   const float* __restrict__ gate_b,
                                                   float* __restrict__ ew_out,
                                                   int write_ew) {
    int b = blockIdx.x;
    int tid = threadIdx.x;
    __shared__ float Ssh[9 * 64];          // [k*64 + c]
    __shared__ float gat[8];

    for (int i = tid; i < 576; i += 256) Ssh[i] = g_S[b*576 + i];
    __syncthreads();

    int warp = tid >> 5, lane = tid & 31;  // warp = expert index
    float acc = 0.f;
    for (int idx = lane; idx < 576; idx += 32) {
        int c = idx / 9;
        int k = idx - c * 9;
        acc += gate_w[warp * 576 + idx] * Ssh[k * 64 + c];
    }
    #pragma unroll
    for (int o = 16; o; o >>= 1) acc += __shfl_down_sync(0xffffffffu, acc, o);
    if (lane == 0) gat[warp] = acc + gate_b[warp] * 3844.0f;  // 62*62 positions
    __syncthreads();

    if (tid == 0) {
        float m = gat[0]; int mi = 0;
        #pragma unroll
        for (int e = 1; e < 8; e++) { if (gat[e] > m) { m = gat[e]; mi = e; } }
        float s = 0.f;
        #pragma unroll
        for (int e = 0; e < 8; e++) s += expf(gat[e] - m);
        g_val[b] = 1.0f / s;
        g_idx[b] = mi;
    }
    __syncthreads();
    if (write_ew && tid < 8) {
        ew_out[b * 8 + tid] = (tid == g_idx[b]) ? g_val[b] : 0.0f;
    }
}

// ===========================================================================
// Kernel 3: mma.sync bf16x3 GEMM.
//   out[b,f,hw] = val[b] * sum_c W[e,f,c] * x[b,c,hw]
//   A = W  (m=f=64, k=c=64, row-major [f][c])  -> ldmatrix.x4, kept in regs
//   B = X  (k=c,    n=hw,   natural  [c][hw])  -> ldmatrix.x2.trans per tile
//   D = [f][hw] fp32, bf16x3: Wh*Xh + Wh*Xl + Wl*Xh
// Block: 128 threads (4 warps), tile f=64 x hw=128, K staged in 2 halves of 32.
// Warp (wf = warp>>1, wn = warp&1): f-slice 32, hw-slice 64.
// smem rows padded so ldmatrix row stride === 4 banks -> conflict-free.
// ===========================================================================
#define WPITCH 36u   // words per W row  (72 bf16 = 64 data + 8 pad)
#define XPITCH 68u   // words per X row  (136 bf16 = 128 data + 8 pad)

__global__ __launch_bounds__(128) void moe_gemm_kernel(const float* __restrict__ x,
                                                       const float* __restrict__ expert_w,
                                                       float* __restrict__ out) {
    __shared__ uint32_t sW[2][64 * WPITCH];   // [hi/lo][f][c-pairs]
    __shared__ uint32_t sX[2][32 * XPITCH];   // [hi/lo][c_local][hw-pairs]

    const int tid  = threadIdx.x;
    const int warp = tid >> 5, lane = tid & 31;
    const int wf   = warp >> 1;         // 0..1 : f group of 32
    const int wn   = warp & 1;          // 0..1 : hw group of 64
    const int b    = blockIdx.y;
    const int hw0  = blockIdx.x * 128;

    const int   e   = g_idx[b];
    const float val = g_val[b];

    const uint32_t swh = smem_u32(sW[0]);
    const uint32_t swl = smem_u32(sW[1]);
    const uint32_t sxh = smem_u32(sX[0]);
    const uint32_t sxl = smem_u32(sX[1]);

    // ---- stage W (hi/lo bf16), rows f, 32 c-pair words ----
    const float* Wsrc = expert_w + (size_t)e * 4096;
    #pragma unroll
    for (int i = 0; i < 16; i++) {
        int p  = tid + i * 128;          // pair index 0..2047
        int f  = p >> 5, cp = p & 31;
        float2 w = *(const float2*)(Wsrc + f * 64 + cp * 2);
        uint32_t hi = pack_bf16x2(w.x, w.y);
        float hx = __uint_as_float(hi << 16);
        float hy = __uint_as_float(hi & 0xffff0000u);
        uint32_t lo = pack_bf16x2(w.x - hx, w.y - hy);
        sW[0][f * WPITCH + cp] = hi;
        sW[1][f * WPITCH + cp] = lo;
    }

    // ---- stage X half 0 (c 0..31) ----
    const float* Xsrc = x + (size_t)b * CC * HWC + hw0;
    #pragma unroll
    for (int i = 0; i < 16; i++) {
        int p = tid + i * 128;           // 0..2047
        int c = p >> 6, hp = p & 63;
        float2 xv = *(const float2*)(Xsrc + (size_t)c * HWC + hp * 2);
        uint32_t hi = pack_bf16x2(xv.x, xv.y);
        float hx = __uint_as_float(hi << 16);
        float hy = __uint_as_float(hi & 0xffff0000u);
        uint32_t lo = pack_bf16x2(xv.x - hx, xv.y - hy);
        sX[0][c * XPITCH + hp] = hi;
        sX[1][c * XPITCH + hp] = lo;
    }
    __syncthreads();

    // ---- A fragments: whole W slice for this warp, all 4 k-tiles, hi+lo ----
    uint32_t aH[2][4][4], aL[2][4][4];
    {
        uint32_t rowsel = (uint32_t)(lane & 15);
        uint32_t seg    = (uint32_t)(lane >> 4) * 16u;
        #pragma unroll
        for (int mt = 0; mt < 2; mt++) {
            uint32_t row = (uint32_t)(wf * 32 + mt * 16) + rowsel;
            #pragma unroll
            for (int kt = 0; kt < 4; kt++) {
                uint32_t off = row * (WPITCH * 4u) + (uint32_t)kt * 32u + seg;
                LDMATRIX_X4(aH[mt][kt], swh + off);
                LDMATRIX_X4(aL[mt][kt], swl + off);
            }
        }
    }

    float acc[2][8][4];
    #pragma unroll
    for (int mt = 0; mt < 2; mt++)
        #pragma unroll
        for (int nt = 0; nt < 8; nt++)
            #pragma unroll
            for (int q = 0; q < 4; q++) acc[mt][nt][q] = 0.f;

    const uint32_t krow = (uint32_t)(lane & 15);

    // ---- mainloop: 2 K-halves x 2 k-tiles x 8 n-tiles ----
    #pragma unroll
    for (int h = 0; h < 2; h++) {
        if (h == 1) {
            __syncthreads();   // everyone done reading half 0
            #pragma unroll
            for (int i = 0; i < 16; i++) {
                int p = tid + i * 128;
                int c = p >> 6, hp = p & 63;
                float2 xv = *(const float2*)(Xsrc + (size_t)(32 + c) * HWC + hp * 2);
                uint32_t hi = pack_bf16x2(xv.x, xv.y);
                float hx = __uint_as_float(hi << 16);
                float hy = __uint_as_float(hi & 0xffff0000u);
                uint32_t lo = pack_bf16x2(xv.x - hx, xv.y - hy);
                sX[0][c * XPITCH + hp] = hi;
                sX[1][c * XPITCH + hp] = lo;
            }
            __syncthreads();
        }
        #pragma unroll
        for (int ktl = 0; ktl < 2; ktl++) {
            int kg = h * 2 + ktl;
            uint32_t kbase = ((uint32_t)(ktl * 16) + krow) * (XPITCH * 4u);
            #pragma unroll
            for (int nt = 0; nt < 8; nt++) {
                uint32_t noff = (uint32_t)(wn * 64 + nt * 8) * 2u;
                uint32_t bh[2], bl[2];
                LDMATRIX_X2T(bh, sxh + kbase + noff);
                LDMATRIX_X2T(bl, sxl + kbase + noff);
                #pragma unroll
                for (int mt = 0; mt < 2; mt++) {
                    MMA_BF16(acc[mt][nt], aH[mt][kg], bh[0], bh[1]);
                    MMA_BF16(acc[mt][nt], aH[mt][kg], bl[0], bl[1]);
                    MMA_BF16(acc[mt][nt], aL[mt][kg], bh[0], bh[1]);
                }
            }
        }
    }

    // ---- epilogue: D[m=f][n=hw]; d0,d1 at (row, col..col+1), d2,d3 at row+8 ----
    float* outb = out + (size_t)b * CC * HWC + hw0;
    int rbase = wf * 32 + (lane >> 2);
    int cbase = wn * 64 + (lane & 3) * 2;
    #pragma unroll
    for (int mt = 0; mt < 2; mt++) {
        #pragma unroll
        for (int nt = 0; nt < 8; nt++) {
            int f0 = rbase + mt * 16;
            int cc = cbase + nt * 8;
            float2 v0 = make_float2(acc[mt][nt][0] * val, acc[mt][nt][1] * val);
            float2 v1 = make_float2(acc[mt][nt][2] * val, acc[mt][nt][3] * val);
            *(float2*)(outb + (size_t)f0 * HWC + cc)       = v0;
            *(float2*)(outb + (size_t)(f0 + 8) * HWC + cc) = v1;
        }
    }
}

// ===========================================================================
extern "C" void kernel_launch(void* const* d_in, const int* in_sizes, int n_in,
                              void* d_out, int out_size) {
    const float* x = nullptr, *gate_w = nullptr, *gate_b = nullptr, *expert_w = nullptr;
    for (int i = 0; i < n_in; i++) {
        switch (in_sizes[i]) {
            case BB*CC*HH*WW: x        = (const float*)d_in[i]; break;  // 524288
            case EE*CC*3*3:   gate_w   = (const float*)d_in[i]; break;  // 4608
            case EE:          gate_b   = (const float*)d_in[i]; break;  // 8
            case EE*CC*CC:    expert_w = (const float*)d_in[i]; break;  // 32768
            default: break;
        }
    }
    float* out = (float*)d_out;
    const int main_elems = BB * CC * HH * WW;
    int write_ew = (out_size >= main_elems + BB * EE) ? 1 : 0;

    region_sums_kernel<<<BB * CC, 128>>>(x);
    gate_kernel<<<BB, 256>>>(gate_w, gate_b, out + main_elems, write_ew);
    moe_gemm_kernel<<<dim3(HWC / 128, BB), 128>>>(x, expert_w, out);
}

// round 5
// speedup vs baseline: 1.9486x; 1.1108x over previous
#include <cuda_runtime.h>
#include <cuda_bf16.h>
#include <cstdint>

#define BB 32
#define CC 64
#define HH 64
#define WW 64
#define EE 8
#define HWC (HH*WW)

// Scratch (device globals: no allocation allowed)
__device__ float g_S[BB * 9 * CC];   // box sums, layout [(b*9+k)*C + c], k = di*3+dj
__device__ float g_val[BB];
__device__ int   g_idx[BB];

// ===========================================================================
// helpers
// ===========================================================================
__device__ __forceinline__ uint32_t smem_u32(const void* p) {
    uint32_t a;
    asm("{ .reg .u64 t; cvta.to.shared.u64 t, %1; cvt.u32.u64 %0, t; }" : "=r"(a) : "l"(p));
    return a;
}

// pack two floats -> bf16x2 word: low 16 bits = 'even', high = 'odd'
__device__ __forceinline__ uint32_t pack_bf16x2(float even, float odd) {
    uint32_t u;
    asm("cvt.rn.bf16x2.f32 %0, %1, %2;" : "=r"(u) : "f"(odd), "f"(even));
    return u;
}

#define LDMATRIX_X4(R, addr) \
    asm volatile("ldmatrix.sync.aligned.m8n8.x4.shared.b16 {%0,%1,%2,%3}, [%4];" \
        : "=r"((R)[0]), "=r"((R)[1]), "=r"((R)[2]), "=r"((R)[3]) : "r"(addr))

#define LDMATRIX_X2T(R, addr) \
    asm volatile("ldmatrix.sync.aligned.m8n8.x2.trans.shared.b16 {%0,%1}, [%2];" \
        : "=r"((R)[0]), "=r"((R)[1]) : "r"(addr))

#define MMA_BF16(D, A, B0, B1) \
    asm volatile("mma.sync.aligned.m16n8k16.row.col.f32.bf16.bf16.f32 " \
        "{%0,%1,%2,%3}, {%4,%5,%6,%7}, {%8,%9}, {%0,%1,%2,%3};" \
        : "+f"((D)[0]), "+f"((D)[1]), "+f"((D)[2]), "+f"((D)[3]) \
        : "r"((A)[0]), "r"((A)[1]), "r"((A)[2]), "r"((A)[3]), "r"(B0), "r"(B1))

// ===========================================================================
// Kernel 1: box sums, fully coalesced.
// Block = one (b,c) image; 128 threads; thread loads float4 at i*128+tid
// (warp instr = 512B contiguous -> 4 L1tex wavefronts, not 32).
// Algebra: sum_rows cv_dj = G - edge-col sums; only rows 0,1,62,63 need
// individual row sums (stored via smem) for the di corrections.
// ===========================================================================
__global__ __launch_bounds__(128) void region_sums_kernel(const float* __restrict__ x) {
    const int tid = threadIdx.x;
    const float4* base = (const float4*)(x + (size_t)blockIdx.x * HWC);
    float4 v[8];
    #pragma unroll
    for (int i = 0; i < 8; i++) v[i] = base[i * 128 + tid];

    const int g  = tid >> 4;   // row group 0..7 ; row = i*8 + g
    const int c4 = tid & 15;   // float4 within row

    __shared__ float sRow[4][16];  // partial sums of edge rows 0,1,62,63
    __shared__ float sRE[4][4];    // edge row elems: x[r][0],[1],[62],[63]
    __shared__ float sCol[4][8];   // per-g partials of cols 0,1,62,63
    __shared__ float sG[4];        // per-warp grand totals

    float gsum = 0.f;
    float ps[8];
    #pragma unroll
    for (int i = 0; i < 8; i++) {
        ps[i] = (v[i].x + v[i].y) + (v[i].z + v[i].w);
        gsum += ps[i];
    }
    // edge rows: row 0 = (i=0,g=0), row 1 = (i=0,g=1), 62 = (i=7,g=6), 63 = (i=7,g=7)
    if (g == 0) sRow[0][c4] = ps[0];
    if (g == 1) sRow[1][c4] = ps[0];
    if (g == 6) sRow[2][c4] = ps[7];
    if (g == 7) sRow[3][c4] = ps[7];
    if (c4 == 0) {
        float cl0 = 0.f, cl1 = 0.f;
        #pragma unroll
        for (int i = 0; i < 8; i++) { cl0 += v[i].x; cl1 += v[i].y; }
        sCol[0][g] = cl0; sCol[1][g] = cl1;
        if (g == 0) { sRE[0][0] = v[0].x; sRE[0][1] = v[0].y; }
        if (g == 1) { sRE[1][0] = v[0].x; sRE[1][1] = v[0].y; }
        if (g == 6) { sRE[2][0] = v[7].x; sRE[2][1] = v[7].y; }
        if (g == 7) { sRE[3][0] = v[7].x; sRE[3][1] = v[7].y; }
    }
    if (c4 == 15) {
        float cr0 = 0.f, cr1 = 0.f;
        #pragma unroll
        for (int i = 0; i < 8; i++) { cr0 += v[i].z; cr1 += v[i].w; }
        sCol[2][g] = cr0; sCol[3][g] = cr1;
        if (g == 0) { sRE[0][2] = v[0].z; sRE[0][3] = v[0].w; }
        if (g == 1) { sRE[1][2] = v[0].z; sRE[1][3] = v[0].w; }
        if (g == 6) { sRE[2][2] = v[7].z; sRE[2][3] = v[7].w; }
        if (g == 7) { sRE[3][2] = v[7].z; sRE[3][3] = v[7].w; }
    }
    #pragma unroll
    for (int o = 16; o; o >>= 1) gsum += __shfl_xor_sync(0xffffffffu, gsum, o);
    if ((tid & 31) == 0) sG[tid >> 5] = gsum;
    __syncthreads();

    if (tid < 9) {
        int di = tid / 3, dj = tid - di * 3;
        float G = (sG[0] + sG[1]) + (sG[2] + sG[3]);
        float c0 = 0.f, c1 = 0.f, c62 = 0.f, c63 = 0.f;
        #pragma unroll
        for (int j = 0; j < 8; j++) {
            c0 += sCol[0][j]; c1 += sCol[1][j]; c62 += sCol[2][j]; c63 += sCol[3][j];
        }
        float colc = (dj == 0) ? (c62 + c63) : (dj == 1) ? (c0 + c63) : (c0 + c1);
        float T = G - colc;                 // sum of cv_dj over all 64 rows
        float rw[4];
        #pragma unroll
        for (int er = 0; er < 4; er++) {
            float s = 0.f;
            #pragma unroll
            for (int j = 0; j < 16; j++) s += sRow[er][j];
            float ec = (dj == 0) ? (sRE[er][2] + sRE[er][3])
                     : (dj == 1) ? (sRE[er][0] + sRE[er][3])
                                 : (sRE[er][0] + sRE[er][1]);
            rw[er] = s - ec;                // cv_dj of that edge row
        }
        float sub = (di == 0) ? (rw[2] + rw[3])
                  : (di == 1) ? (rw[0] + rw[3])
                              : (rw[0] + rw[1]);
        int b = blockIdx.x >> 6, c = blockIdx.x & 63;
        g_S[(b * 9 + tid) * CC + c] = T - sub;
    }
}

// ===========================================================================
// Kernel 2: gating dot products, softmax, top-1, expert_weights output.
// ===========================================================================
__global__ __launch_bounds__(256) void gate_kernel(const float* __restrict__ gate_w,
                                                   const float* __restrict__ gate_b,
                                                   float* __restrict__ ew_out,
                                                   int write_ew) {
    int b = blockIdx.x;
    int tid = threadIdx.x;
    __shared__ float Ssh[9 * 64];          // [k*64 + c]
    __shared__ float gat[8];

    for (int i = tid; i < 576; i += 256) Ssh[i] = g_S[b*576 + i];
    __syncthreads();

    int warp = tid >> 5, lane = tid & 31;  // warp = expert index
    float acc = 0.f;
    for (int idx = lane; idx < 576; idx += 32) {
        int c = idx / 9;
        int k = idx - c * 9;
        acc += gate_w[warp * 576 + idx] * Ssh[k * 64 + c];
    }
    #pragma unroll
    for (int o = 16; o; o >>= 1) acc += __shfl_down_sync(0xffffffffu, acc, o);
    if (lane == 0) gat[warp] = acc + gate_b[warp] * 3844.0f;  // 62*62 positions
    __syncthreads();

    if (tid == 0) {
        float m = gat[0]; int mi = 0;
        #pragma unroll
        for (int e = 1; e < 8; e++) { if (gat[e] > m) { m = gat[e]; mi = e; } }
        float s = 0.f;
        #pragma unroll
        for (int e = 0; e < 8; e++) s += expf(gat[e] - m);
        g_val[b] = 1.0f / s;
        g_idx[b] = mi;
    }
    __syncthreads();
    if (write_ew && tid < 8) {
        ew_out[b * 8 + tid] = (tid == g_idx[b]) ? g_val[b] : 0.0f;
    }
}

// ===========================================================================
// Kernel 3: mma.sync bf16x3 GEMM (unchanged from R4 win).
//   out[b,f,hw] = val[b] * sum_c W[e,f,c] * x[b,c,hw]
//   A = W  (m=f=64, k=c=64, row-major [f][c])  -> ldmatrix.x4, kept in regs
//   B = X  (k=c,    n=hw,   natural  [c][hw])  -> ldmatrix.x2.trans per tile
//   D = [f][hw] fp32, bf16x3: Wh*Xh + Wh*Xl + Wl*Xh
// ===========================================================================
#define WPITCH 36u   // words per W row  (72 bf16 = 64 data + 8 pad)
#define XPITCH 68u   // words per X row  (136 bf16 = 128 data + 8 pad)

__global__ __launch_bounds__(128) void moe_gemm_kernel(const float* __restrict__ x,
                                                       const float* __restrict__ expert_w,
                                                       float* __restrict__ out) {
    __shared__ uint32_t sW[2][64 * WPITCH];   // [hi/lo][f][c-pairs]
    __shared__ uint32_t sX[2][32 * XPITCH];   // [hi/lo][c_local][hw-pairs]

    const int tid  = threadIdx.x;
    const int warp = tid >> 5, lane = tid & 31;
    const int wf   = warp >> 1;         // 0..1 : f group of 32
    const int wn   = warp & 1;          // 0..1 : hw group of 64
    const int b    = blockIdx.y;
    const int hw0  = blockIdx.x * 128;

    const int   e   = g_idx[b];
    const float val = g_val[b];

    const uint32_t swh = smem_u32(sW[0]);
    const uint32_t swl = smem_u32(sW[1]);
    const uint32_t sxh = smem_u32(sX[0]);
    const uint32_t sxl = smem_u32(sX[1]);

    // ---- stage W (hi/lo bf16), rows f, 32 c-pair words ----
    const float* Wsrc = expert_w + (size_t)e * 4096;
    #pragma unroll
    for (int i = 0; i < 16; i++) {
        int p  = tid + i * 128;          // pair index 0..2047
        int f  = p >> 5, cp = p & 31;
        float2 w = *(const float2*)(Wsrc + f * 64 + cp * 2);
        uint32_t hi = pack_bf16x2(w.x, w.y);
        float hx = __uint_as_float(hi << 16);
        float hy = __uint_as_float(hi & 0xffff0000u);
        uint32_t lo = pack_bf16x2(w.x - hx, w.y - hy);
        sW[0][f * WPITCH + cp] = hi;
        sW[1][f * WPITCH + cp] = lo;
    }

    // ---- stage X half 0 (c 0..31) ----
    const float* Xsrc = x + (size_t)b * CC * HWC + hw0;
    #pragma unroll
    for (int i = 0; i < 16; i++) {
        int p = tid + i * 128;           // 0..2047
        int c = p >> 6, hp = p & 63;
        float2 xv = *(const float2*)(Xsrc + (size_t)c * HWC + hp * 2);
        uint32_t hi = pack_bf16x2(xv.x, xv.y);
        float hx = __uint_as_float(hi << 16);
        float hy = __uint_as_float(hi & 0xffff0000u);
        uint32_t lo = pack_bf16x2(xv.x - hx, xv.y - hy);
        sX[0][c * XPITCH + hp] = hi;
        sX[1][c * XPITCH + hp] = lo;
    }
    __syncthreads();

    // ---- A fragments: whole W slice for this warp, all 4 k-tiles, hi+lo ----
    uint32_t aH[2][4][4], aL[2][4][4];
    {
        uint32_t rowsel = (uint32_t)(lane & 15);
        uint32_t seg    = (uint32_t)(lane >> 4) * 16u;
        #pragma unroll
        for (int mt = 0; mt < 2; mt++) {
            uint32_t row = (uint32_t)(wf * 32 + mt * 16) + rowsel;
            #pragma unroll
            for (int kt = 0; kt < 4; kt++) {
                uint32_t off = row * (WPITCH * 4u) + (uint32_t)kt * 32u + seg;
                LDMATRIX_X4(aH[mt][kt], swh + off);
                LDMATRIX_X4(aL[mt][kt], swl + off);
            }
        }
    }

    float acc[2][8][4];
    #pragma unroll
    for (int mt = 0; mt < 2; mt++)
        #pragma unroll
        for (int nt = 0; nt < 8; nt++)
            #pragma unroll
            for (int q = 0; q < 4; q++) acc[mt][nt][q] = 0.f;

    const uint32_t krow = (uint32_t)(lane & 15);

    // ---- mainloop: 2 K-halves x 2 k-tiles x 8 n-tiles ----
    #pragma unroll
    for (int h = 0; h < 2; h++) {
        if (h == 1) {
            __syncthreads();   // everyone done reading half 0
            #pragma unroll
            for (int i = 0; i < 16; i++) {
                int p = tid + i * 128;
                int c = p >> 6, hp = p & 63;
                float2 xv = *(const float2*)(Xsrc + (size_t)(32 + c) * HWC + hp * 2);
                uint32_t hi = pack_bf16x2(xv.x, xv.y);
                float hx = __uint_as_float(hi << 16);
                float hy = __uint_as_float(hi & 0xffff0000u);
                uint32_t lo = pack_bf16x2(xv.x - hx, xv.y - hy);
                sX[0][c * XPITCH + hp] = hi;
                sX[1][c * XPITCH + hp] = lo;
            }
            __syncthreads();
        }
        #pragma unroll
        for (int ktl = 0; ktl < 2; ktl++) {
            int kg = h * 2 + ktl;
            uint32_t kbase = ((uint32_t)(ktl * 16) + krow) * (XPITCH * 4u);
            #pragma unroll
            for (int nt = 0; nt < 8; nt++) {
                uint32_t noff = (uint32_t)(wn * 64 + nt * 8) * 2u;
                uint32_t bh[2], bl[2];
                LDMATRIX_X2T(bh, sxh + kbase + noff);
                LDMATRIX_X2T(bl, sxl + kbase + noff);
                #pragma unroll
                for (int mt = 0; mt < 2; mt++) {
                    MMA_BF16(acc[mt][nt], aH[mt][kg], bh[0], bh[1]);
                    MMA_BF16(acc[mt][nt], aH[mt][kg], bl[0], bl[1]);
                    MMA_BF16(acc[mt][nt], aL[mt][kg], bh[0], bh[1]);
                }
            }
        }
    }

    // ---- epilogue: D[m=f][n=hw]; d0,d1 at (row, col..col+1), d2,d3 at row+8 ----
    float* outb = out + (size_t)b * CC * HWC + hw0;
    int rbase = wf * 32 + (lane >> 2);
    int cbase = wn * 64 + (lane & 3) * 2;
    #pragma unroll
    for (int mt = 0; mt < 2; mt++) {
        #pragma unroll
        for (int nt = 0; nt < 8; nt++) {
            int f0 = rbase + mt * 16;
            int cc = cbase + nt * 8;
            float2 v0 = make_float2(acc[mt][nt][0] * val, acc[mt][nt][1] * val);
            float2 v1 = make_float2(acc[mt][nt][2] * val, acc[mt][nt][3] * val);
            *(float2*)(outb + (size_t)f0 * HWC + cc)       = v0;
            *(float2*)(outb + (size_t)(f0 + 8) * HWC + cc) = v1;
        }
    }
}

// ===========================================================================
extern "C" void kernel_launch(void* const* d_in, const int* in_sizes, int n_in,
                              void* d_out, int out_size) {
    const float* x = nullptr, *gate_w = nullptr, *gate_b = nullptr, *expert_w = nullptr;
    for (int i = 0; i < n_in; i++) {
        switch (in_sizes[i]) {
            case BB*CC*HH*WW: x        = (const float*)d_in[i]; break;  // 524288
            case EE*CC*3*3:   gate_w   = (const float*)d_in[i]; break;  // 4608
            case EE:          gate_b   = (const float*)d_in[i]; break;  // 8
            case EE*CC*CC:    expert_w = (const float*)d_in[i]; break;  // 32768
            default: break;
        }
    }
    float* out = (float*)d_out;
    const int main_elems = BB * CC * HH * WW;
    int write_ew = (out_size >= main_elems + BB * EE) ? 1 : 0;

    region_sums_kernel<<<BB * CC, 128>>>(x);
    gate_kernel<<<BB, 256>>>(gate_w, gate_b, out + main_elems, write_ew);
    moe_gemm_kernel<<<dim3(HWC / 128, BB), 128>>>(x, expert_w, out);
}